// round 3
// baseline (speedup 1.0000x reference)
#include <cuda_runtime.h>
#include <math.h>

#define NN 8192
#define EE 262144
#define CC 64
#define NMASK (NN - 1)
#define ELLW 96

typedef unsigned long long u64;

// ---- static device scratch (zero-initialized at module load) ----
__device__ u64   g_map[(size_t)NN * NN];   // epoch-tagged last-write-wins map (never reset)
__device__ u64   g_epoch;                  // bumped at end of each launch
__device__ int   g_rowcnt[NN];
__device__ float g_deg[NN];
__device__ float g_dinv[NN];
__device__ u64   g_ell[NN * ELLW];         // packed (w<<32 | col)
__device__ float g_tx1[NN * CC];
__device__ float g_sig;

// ---- K1: init + mark max tag per (row,col) ----
__global__ void k_pass1(const int* __restrict__ ei, const float* __restrict__ adaptive) {
    int e = blockIdx.x * blockDim.x + threadIdx.x;
    if (e < NN) {                 // fused per-launch init
        g_deg[e] = 1.0f;          // identity contribution to degree
        g_rowcnt[e] = 0;
    }
    if (e == 0) g_sig = 1.0f / (1.0f + expf(-adaptive[0]));
    if (e >= EE) return;
    int r = ei[e] & NMASK;
    int c = ei[EE + e] & NMASK;
    u64 tag = ((g_epoch + 1) << 20) | (u64)(e + 1);
    atomicMax(&g_map[(size_t)r * NN + c], tag);
}

// ---- K2: winners -> ELL slots + degree ----
__global__ void k_pass2(const int* __restrict__ ei, const float* __restrict__ ew) {
    int e = blockIdx.x * blockDim.x + threadIdx.x;
    if (e >= EE) return;
    int r = ei[e] & NMASK;
    int c = ei[EE + e] & NMASK;
    u64 tag = ((g_epoch + 1) << 20) | (u64)(e + 1);
    if (g_map[(size_t)r * NN + c] == tag) {
        float aw = ew[e] * g_sig;
        int pos = atomicAdd(&g_rowcnt[r], 1);
        if (pos < ELLW) {
            u64 pk = ((u64)__float_as_uint(aw) << 32) | (u64)c;
            g_ell[r * ELLW + pos] = pk;
        }
        atomicAdd(&g_deg[r], aw);
    }
}

// ---- K3: dinv = deg^-1/2 ----
__global__ void k_dinv() {
    int i = blockIdx.x * blockDim.x + threadIdx.x;
    if (i < NN) g_dinv[i] = rsqrtf(g_deg[i]);
}

// ---- SpMM helper: y[row][t] of L @ xin ----
// (L x)[r] = x[r] - dinv[r] * ( dinv[r]*x[r] + sum_slots w * dinv[col] * x[col] )
__device__ __forceinline__ float lx_row(const float* __restrict__ xin,
                                        int row, int t) {
    float di = g_dinv[row];
    float xr = xin[row * CC + t];
    float acc = di * xr;                   // identity (+I) term
    int cnt = g_rowcnt[row];
    if (cnt > ELLW) cnt = ELLW;
    const u64* ell = &g_ell[row * ELLW];
    for (int k = 0; k < cnt; k++) {
        u64 pk = __ldg(&ell[k]);
        int col = (int)(pk & 0xffffffffu);
        float w = __uint_as_float((unsigned)(pk >> 32));
        acc += (w * g_dinv[col]) * xin[col * CC + t];
    }
    return xr - di * acc;
}

// ---- K4: tx1 = L @ x ----
__global__ void k_spmm1(const float* __restrict__ x) {
    int row = blockIdx.x * blockDim.y + threadIdx.y;
    int t = threadIdx.x;
    g_tx1[row * CC + t] = lx_row(x, row, t);
}

// ---- K5: tx2 = 2*(L @ tx1) - x (smem), then out = x@W0 + tx1@W1 + tx2@W2 + b ----
__global__ void k_spmm2_gemm(const float* __restrict__ x,
                             const float* __restrict__ W,
                             const float* __restrict__ bias,
                             float* __restrict__ out) {
    __shared__ float sW[3 * CC * CC];      // 48 KB
    __shared__ float stx2[32][CC];         // 8 KB
    int o = threadIdx.x;                   // out channel / channel lane
    int ry = threadIdx.y;                  // 0..3
    int tid = ry * 64 + o;
    for (int i = tid; i < 3 * CC * CC; i += 256) sW[i] = W[i];

    int rbase = blockIdx.x * 32;
#pragma unroll
    for (int i = 0; i < 8; i++) {
        int lr = i * 4 + ry;
        int gr = rbase + lr;
        float y = lx_row(g_tx1, gr, o);
        stx2[lr][o] = 2.0f * y - x[gr * CC + o];
    }
    __syncthreads();

    float b = bias[o];
#pragma unroll
    for (int i = 0; i < 8; i++) {
        int lr = i * 4 + ry;
        int gr = rbase + lr;
        float acc = b;
        const float* x0 = x + gr * CC;
        const float* x1 = g_tx1 + gr * CC;
#pragma unroll 4
        for (int c = 0; c < CC; c++) {
            acc += x0[c] * sW[c * CC + o];
            acc += x1[c] * sW[CC * CC + c * CC + o];
            acc += stx2[lr][c] * sW[2 * CC * CC + c * CC + o];
        }
        out[gr * CC + o] = acc;
    }

    if (blockIdx.x == 0 && tid == 0) g_epoch += 1;  // stable during this launch
}

extern "C" void kernel_launch(void* const* d_in, const int* in_sizes, int n_in,
                              void* d_out, int out_size) {
    const float* x        = (const float*)d_in[0];
    const int*   ei       = (const int*)d_in[1];
    const float* ew       = (const float*)d_in[2];
    const float* W        = (const float*)d_in[3];
    const float* adaptive = (const float*)d_in[4];
    const float* bias     = (const float*)d_in[5];
    float* out = (float*)d_out;

    k_pass1<<<EE / 256, 256>>>(ei, adaptive);
    k_pass2<<<EE / 256, 256>>>(ei, ew);
    k_dinv<<<NN / 256, 256>>>();
    k_spmm1<<<NN / 4, dim3(64, 4)>>>(x);
    k_spmm2_gemm<<<NN / 32, dim3(64, 4)>>>(x, W, bias, out);
}

// round 4
// speedup vs baseline: 1.9886x; 1.9886x over previous
#include <cuda_runtime.h>
#include <math.h>

#define NN 8192
#define EE 262144
#define CC 64
#define NMASK (NN - 1)
#define ELLW 96

typedef unsigned long long u64;

// ---- static device scratch (zero-initialized at module load) ----
__device__ int   g_map[(size_t)NN * NN];   // LWW map: holds e+1 during a launch, reset by winners
__device__ int   g_rowcnt[NN];
__device__ float g_deg[NN];
__device__ float g_dinv[NN];
__device__ u64   g_ell[NN * ELLW];         // packed (w_bits<<32 | col)
__device__ float g_z[NN * CC];             // dinv * x
__device__ float g_tx1[NN * CC];
__device__ float g_zt[NN * CC];            // dinv * tx1
__device__ float g_sig;

// ---- K1: fused init + mark max edge id per (row,col) ----
__global__ void k_pass1(const int* __restrict__ ei, const float* __restrict__ adaptive) {
    int e = blockIdx.x * blockDim.x + threadIdx.x;
    if (e < NN) {
        g_deg[e] = 1.0f;                   // identity contribution to degree
        g_rowcnt[e] = 0;
    }
    if (e == 0) g_sig = 1.0f / (1.0f + expf(-adaptive[0]));
    if (e >= EE) return;
    int r = ei[e] & NMASK;
    int c = ei[EE + e] & NMASK;
    atomicMax(&g_map[r * NN + c], e + 1);
}

// ---- K2: winners -> ELL + degree, and winner resets its map cell ----
// After the launch boundary map[key] is the final max; the ONLY pass-2 write
// to a cell is its unique winner's 0-store, so losers read {final_max, 0},
// both != their own tag. Race-free reset; no third edge pass needed.
__global__ void k_pass2(const int* __restrict__ ei, const float* __restrict__ ew) {
    int e = blockIdx.x * blockDim.x + threadIdx.x;
    if (e >= EE) return;
    int r = ei[e] & NMASK;
    int c = ei[EE + e] & NMASK;
    int key = r * NN + c;
    if (g_map[key] == e + 1) {
        float aw = ew[e] * g_sig;
        int pos = atomicAdd(&g_rowcnt[r], 1);
        if (pos < ELLW) {
            u64 pk = ((u64)__float_as_uint(aw) << 32) | (u64)(unsigned)c;
            g_ell[r * ELLW + pos] = pk;
        }
        atomicAdd(&g_deg[r], aw);
        g_map[key] = 0;                    // self-cleaning for next launch
    }
}

// ---- K3: dinv + z = dinv*x (float2 over NN*32) ----
__global__ void k_prep(const float* __restrict__ x) {
    int i = blockIdx.x * blockDim.x + threadIdx.x;
    if (i >= NN * 32) return;
    int row = i >> 5;
    float di = rsqrtf(g_deg[row]);
    float2 v = ((const float2*)x)[i];
    v.x *= di; v.y *= di;
    ((float2*)g_z)[i] = v;
    if ((i & 31) == 0) g_dinv[row] = di;
}

// ---- K4: tx1 = L @ x ; zt = dinv*tx1. One warp per row, float2 channels ----
__global__ void k_spmm1(const float* __restrict__ x) {
    int row = blockIdx.x * 8 + threadIdx.y;
    int t = threadIdx.x;                   // channel pair 0..31
    const float2* z2 = (const float2*)g_z;
    float2 acc = z2[row * 32 + t];         // identity term (dinv*x[row])
    int cnt = g_rowcnt[row]; if (cnt > ELLW) cnt = ELLW;
    float di = g_dinv[row];
    const u64* ell = &g_ell[row * ELLW];
    for (int k = 0; k < cnt; k++) {
        u64 pk = __ldg(&ell[k]);
        int col = (int)(pk & 0xffffffffu);
        float w = __uint_as_float((unsigned)(pk >> 32));
        float2 zc = z2[col * 32 + t];
        acc.x += w * zc.x; acc.y += w * zc.y;
    }
    float2 xr = ((const float2*)x)[row * 32 + t];
    float2 y; y.x = xr.x - di * acc.x; y.y = xr.y - di * acc.y;
    ((float2*)g_tx1)[row * 32 + t] = y;
    float2 zt; zt.x = di * y.x; zt.y = di * y.y;
    ((float2*)g_zt)[row * 32 + t] = zt;
}

// ---- K5: tx2 = 2*(L@tx1) - x (smem only), out = x@W0 + tx1@W1 + tx2@W2 + b ----
extern __shared__ float s_dyn[];
__global__ void k_fuse(const float* __restrict__ x,
                       const float* __restrict__ W,
                       const float* __restrict__ bias,
                       float* __restrict__ out) {
    float* sW   = s_dyn;                   // 3*64*64
    float* sx   = sW + 3 * CC * CC;        // 32*64
    float* stx1 = sx + 32 * CC;            // 32*64
    float* stx2 = stx1 + 32 * CC;          // 32*64
    int t = threadIdx.x, ty = threadIdx.y;
    int tid = ty * 32 + t;
    for (int i = tid; i < 3 * CC * CC; i += 256) sW[i] = W[i];

    int rbase = blockIdx.x * 32;
    const float2* zt2 = (const float2*)g_zt;
#pragma unroll
    for (int i = 0; i < 4; i++) {
        int lr = i * 8 + ty;
        int row = rbase + lr;
        float2 acc = zt2[row * 32 + t];
        int cnt = g_rowcnt[row]; if (cnt > ELLW) cnt = ELLW;
        float di = g_dinv[row];
        const u64* ell = &g_ell[row * ELLW];
        for (int k = 0; k < cnt; k++) {
            u64 pk = __ldg(&ell[k]);
            int col = (int)(pk & 0xffffffffu);
            float w = __uint_as_float((unsigned)(pk >> 32));
            float2 zc = zt2[col * 32 + t];
            acc.x += w * zc.x; acc.y += w * zc.y;
        }
        float2 x1 = ((const float2*)g_tx1)[row * 32 + t];
        float2 x0 = ((const float2*)x)[row * 32 + t];
        float yx = x1.x - di * acc.x;
        float yy = x1.y - di * acc.y;
        sx[lr * CC + 2 * t]       = x0.x;  sx[lr * CC + 2 * t + 1]   = x0.y;
        stx1[lr * CC + 2 * t]     = x1.x;  stx1[lr * CC + 2 * t + 1] = x1.y;
        stx2[lr * CC + 2 * t]     = 2.0f * yx - x0.x;
        stx2[lr * CC + 2 * t + 1] = 2.0f * yy - x0.y;
    }
    __syncthreads();

    float b0 = bias[t], b1 = bias[t + 32];
#pragma unroll
    for (int j = 0; j < 4; j++) {
        int lr = j * 8 + ty;
        float a0 = b0, a1 = b1;
#pragma unroll
        for (int c = 0; c < CC; c++) {
            float v0 = sx[lr * CC + c];
            float v1 = stx1[lr * CC + c];
            float v2 = stx2[lr * CC + c];
            a0 += v0 * sW[c * CC + t]       + v1 * sW[CC*CC + c * CC + t]       + v2 * sW[2*CC*CC + c * CC + t];
            a1 += v0 * sW[c * CC + t + 32]  + v1 * sW[CC*CC + c * CC + t + 32]  + v2 * sW[2*CC*CC + c * CC + t + 32];
        }
        int row = rbase + lr;
        out[row * CC + t]      = a0;
        out[row * CC + t + 32] = a1;
    }
}

extern "C" void kernel_launch(void* const* d_in, const int* in_sizes, int n_in,
                              void* d_out, int out_size) {
    const float* x        = (const float*)d_in[0];
    const int*   ei       = (const int*)d_in[1];
    const float* ew       = (const float*)d_in[2];
    const float* W        = (const float*)d_in[3];
    const float* adaptive = (const float*)d_in[4];
    const float* bias     = (const float*)d_in[5];
    float* out = (float*)d_out;

    const int fuse_smem = (3 * CC * CC + 3 * 32 * CC) * sizeof(float);  // 72 KB
    cudaFuncSetAttribute(k_fuse, cudaFuncAttributeMaxDynamicSharedMemorySize, fuse_smem);

    k_pass1<<<EE / 256, 256>>>(ei, adaptive);
    k_pass2<<<EE / 256, 256>>>(ei, ew);
    k_prep<<<(NN * 32) / 256, 256>>>(x);
    k_spmm1<<<NN / 8, dim3(32, 8)>>>(x);
    k_fuse<<<NN / 32, dim3(32, 8), fuse_smem>>>(x, W, bias, out);
}